// round 14
// baseline (speedup 1.0000x reference)
#include <cuda_runtime.h>

// QPSolver: N=32, M=64, BS=512, ITERS=1000, ALPHA=BETA=1
// Out layout (float32): Xs (512,1001,128) then primal_sols (512,1001,32).

#define BSZ   512
#define NDIM  32
#define MDIM  64
#define ITERS 1000

typedef unsigned long long ull;

__device__ __align__(16) float gD[MDIM * MDIM];      // D = H P^-1 H^T
__device__ __align__(16) float gHinv[NDIM * MDIM];   // pinv(H) (32x64)
__device__ __align__(16) float gWq[NDIM * MDIM];     // P^-1 H^T (32x64)
__device__ float gC;                                 // 1/lambda_max(D)

#define FMA2(acc, x, y) asm("fma.rn.f32x2 %0,%1,%2,%0;" : "+l"(acc) : "l"(x), "l"(y))
#define MUL2(d, x, y)   asm("mul.rn.f32x2 %0,%1,%2;" : "=l"(d) : "l"(x), "l"(y))

__device__ __forceinline__ float red4(ull a0, ull a1, ull a2, ull a3) {
    ull s0, s1, s;
    asm("add.rn.f32x2 %0,%1,%2;" : "=l"(s0) : "l"(a0), "l"(a1));
    asm("add.rn.f32x2 %0,%1,%2;" : "=l"(s1) : "l"(a2), "l"(a3));
    asm("add.rn.f32x2 %0,%1,%2;" : "=l"(s)  : "l"(s0), "l"(s1));
    unsigned lo, hi;
    asm("mov.b64 {%0,%1},%2;" : "=r"(lo), "=r"(hi) : "l"(s));
    return __uint_as_float(lo) + __uint_as_float(hi);
}
__device__ __forceinline__ ull dup2(float a) {
    ull r; asm("mov.b64 %0,{%1,%1};" : "=l"(r) : "f"(a)); return r;
}

// ---------------------------------------------------------------------------
// Warp-scope Gauss-Jordan on a 32 x 96 system, rows in registers, shfl
// broadcast, NO barriers, NO pivoting (SPD left block). Lane l holds row l.
// ---------------------------------------------------------------------------
__device__ __forceinline__ void gj_warp(float a[96], int lane) {
    for (int c = 0; c < 32; c++) {
        float myc = 0.0f;
#pragma unroll
        for (int j = 0; j < 32; j++) if (j == c) myc = a[j];
        float pv = __shfl_sync(0xffffffffu, myc, c);
        float inv = 1.0f / pv;
        float f = myc * inv;
        bool isp = (lane == c);
#pragma unroll
        for (int j = 0; j < 96; j++) {
            float pr = __shfl_sync(0xffffffffu, a[j], c);
            a[j] = isp ? pr * inv : fmaf(-f, pr, a[j]);
        }
    }
}

// ---------------------------------------------------------------------------
// Setup (1 block, 256 threads) — unchanged from R13.
// ---------------------------------------------------------------------------
__global__ void __launch_bounds__(256) setup_kernel(
    const float* __restrict__ P, const float* __restrict__ H)
{
    __shared__ __align__(16) float sH[2048];       // H (64x32)
    __shared__ __align__(16) float sWq[2048];      // Wq (32x64)
    __shared__ __align__(16) float sB[2][32 * 34]; // B buffers, pitch 34
    __shared__ float sV[32];

    int t = threadIdx.x, lane = t & 31, w = t >> 5;

    for (int i = t; i < 2048; i += 256) sH[i] = H[i];
    __syncthreads();

    if (w == 0) {
        float a[96];
#pragma unroll
        for (int j = 0; j < 32; j++) a[j] = P[lane * 32 + j];
#pragma unroll
        for (int j = 0; j < 64; j++) a[32 + j] = sH[j * 32 + lane];
        gj_warp(a, lane);
#pragma unroll
        for (int j = 0; j < 64; j++) {
            sWq[lane * 64 + j] = a[32 + j];
            gWq[lane * 64 + j] = a[32 + j];
        }
    } else if (w == 1) {
        ull acc[16];
#pragma unroll
        for (int j = 0; j < 16; j++) acc[j] = 0ull;
        for (int kk = 0; kk < 64; kk++) {
            ull hl = dup2(sH[kk * 32 + lane]);
            const ull* hr = (const ull*)(sH + kk * 32);
#pragma unroll
            for (int j = 0; j < 16; j++) FMA2(acc[j], hl, hr[j]);
        }
        float a[96];
#pragma unroll
        for (int j = 0; j < 16; j++) {
            unsigned lo, hi;
            asm("mov.b64 {%0,%1},%2;" : "=r"(lo), "=r"(hi) : "l"(acc[j]));
            a[2 * j] = __uint_as_float(lo);
            a[2 * j + 1] = __uint_as_float(hi);
        }
#pragma unroll
        for (int j = 0; j < 64; j++) a[32 + j] = sH[j * 32 + lane];
        gj_warp(a, lane);
#pragma unroll
        for (int j = 0; j < 64; j++) gHinv[lane * 64 + j] = a[32 + j];
    }
    __syncthreads();

    // D = H * Wq (64x64) -> gD
    {
        int r = t >> 2, cb = (t & 3) * 8;
        ull acc[8];
#pragma unroll
        for (int j = 0; j < 8; j++) acc[j] = 0ull;
        for (int kk = 0; kk < 32; kk++) {
            ull ap = dup2(sH[r * 32 + kk]);
            const ull* rw = (const ull*)(sWq + kk * 64);
#pragma unroll
            for (int j = 0; j < 8; j++) FMA2(acc[j], ap, rw[cb + j]);
        }
        ull* grow = (ull*)(gD + r * 64);
#pragma unroll
        for (int j = 0; j < 8; j++) grow[cb + j] = acc[j];
    }

    // warp0: eigen path on B = Wq @ H (32x32)
    if (w == 0) {
        float ts[6];
        {
            ull bacc[16];
#pragma unroll
            for (int j = 0; j < 16; j++) bacc[j] = 0ull;
            for (int k = 0; k < 64; k++) {
                ull ap = dup2(sWq[lane * 64 + k]);
                const ull* hr = (const ull*)(sH + k * 32);
#pragma unroll
                for (int j = 0; j < 16; j++) FMA2(bacc[j], ap, hr[j]);
            }
            ull* dr = (ull*)(sB[0] + lane * 34);
#pragma unroll
            for (int j = 0; j < 16; j++) dr[j] = bacc[j];
        }
        __syncwarp();
        {
            float tr = sB[0][lane * 34 + lane];
            for (int o = 16; o; o >>= 1) tr += __shfl_xor_sync(0xffffffffu, tr, o);
            ts[0] = tr;
            ull iv = dup2(1.0f / tr);
            ull* dr = (ull*)(sB[0] + lane * 34);
#pragma unroll
            for (int j = 0; j < 16; j++) { ull v = dr[j]; MUL2(v, v, iv); dr[j] = v; }
        }
        __syncwarp();
        for (int s = 1; s <= 5; s++) {
            const float* src = sB[(s - 1) & 1];
            float* dst = sB[s & 1];
            ull cacc[16];
#pragma unroll
            for (int j = 0; j < 16; j++) cacc[j] = 0ull;
            for (int k = 0; k < 32; k++) {
                ull ap = dup2(src[lane * 34 + k]);
                const ull* rw = (const ull*)(src + k * 34);
#pragma unroll
                for (int j = 0; j < 16; j++) FMA2(cacc[j], ap, rw[j]);
            }
            ull* dr = (ull*)(dst + lane * 34);
#pragma unroll
            for (int j = 0; j < 16; j++) dr[j] = cacc[j];
            __syncwarp();
            float tr = dst[lane * 34 + lane];
            for (int o = 16; o; o >>= 1) tr += __shfl_xor_sync(0xffffffffu, tr, o);
            ts[s] = tr;
            ull iv = dup2(1.0f / tr);
#pragma unroll
            for (int j = 0; j < 16; j++) { ull v = dr[j]; MUL2(v, v, iv); dr[j] = v; }
            __syncwarp();
        }
        const float* Bs = sB[1];
        float v = 1.0f + 0.001f * (float)lane;
        sV[lane] = v;
        __syncwarp();
        float wv = 0.0f;
        for (int it = 0; it <= 16; it++) {
            wv = 0.0f;
            for (int k = 0; k < 32; k++) wv = fmaf(Bs[lane * 34 + k], sV[k], wv);
            if (it == 16) break;
            float m = fabsf(wv);
            for (int o = 16; o; o >>= 1) m = fmaxf(m, __shfl_xor_sync(0xffffffffu, m, o));
            v = wv * (1.0f / m);
            sV[lane] = v;
            __syncwarp();
        }
        float num = v * wv, den = v * v;
        for (int o = 16; o; o >>= 1) {
            num += __shfl_xor_sync(0xffffffffu, num, o);
            den += __shfl_xor_sync(0xffffffffu, den, o);
        }
        if (lane == 0) {
            double lam = (double)num / (double)den;
            for (int s = 5; s >= 1; s--) lam = sqrt((double)ts[s] * lam);
            gC = (float)(1.0 / ((double)ts[0] * lam));
        }
    }
}

// ---------------------------------------------------------------------------
// Solver: warp-per-row, 4 rows/block, grid 128 (1 warp/SMSP), no barriers in
// the hot loop. Typed C++ shared accesses (compiler-schedulable); asm only
// for register-pure f32x2 FMAs. Loop unrolled x2 (static buffer indices).
// Primal pairs p(2t), p(2t+1) between the half-iterations so each per-lane
// Hinv load serves two z vectors.
// ---------------------------------------------------------------------------
__global__ void __launch_bounds__(128, 1) solve_kernel(
    const float* __restrict__ q, const float* __restrict__ b, float* __restrict__ out)
{
    __shared__ __align__(16) float sHinv[32 * 68];   // back half used in loop
    __shared__ __align__(16) float sy[4][2][64];
    __shared__ __align__(16) float sz[4][2][64];

    int t = threadIdx.x, lane = t & 31, w = t >> 5;
    int row = blockIdx.x * 4 + w;

    for (int i = t; i < 2048; i += 128)
        sHinv[(i >> 6) * 68 + (i & 63)] = gHinv[i];
    __syncthreads();                                  // only barrier

    float c = gC;

    // D rows lane and lane+32 resident (64 ull = 128 regs)
    ull dA2[32], dB2[32];
    const ull* gD2 = (const ull*)gD;
#pragma unroll
    for (int i = 0; i < 32; i++) {
        dA2[i] = gD2[lane * 32 + i];
        dB2[i] = gD2[(lane + 32) * 32 + i];
    }
    // Hinv front half (k = 0..31) resident (16 ull = 32 regs)
    ull hv[16];
    const ull* gH2 = (const ull*)gHinv;
#pragma unroll
    for (int i = 0; i < 16; i++) hv[i] = gH2[lane * 32 + i];

    const float* qr = q + row * NDIM;
    const float* br = b + (size_t)row * MDIM;
    float mu0 = 0.0f, mu1 = 0.0f;
#pragma unroll
    for (int i = 0; i < 32; i++) {
        float qi = qr[i];
        mu0 = fmaf(qi, gWq[i * 64 + lane], mu0);
        mu1 = fmaf(qi, gWq[i * 64 + lane + 32], mu1);
    }
    mu0 = c * (mu0 - br[lane]);
    mu1 = c * (mu1 - br[lane + 32]);

    // hb = Hinv[lane] . b_row  (front from regs, back from shared)
    float hb;
    {
        const ull* b2 = (const ull*)br;
        ull a0 = 0ull, a1 = 0ull, a2 = 0ull, a3 = 0ull;
#pragma unroll
        for (int i = 0; i < 8; i++) {
            FMA2(a0, hv[2 * i], b2[2 * i]);
            FMA2(a1, hv[2 * i + 1], b2[2 * i + 1]);
        }
        const ull* hs = (const ull*)(sHinv + lane * 68 + 32);
#pragma unroll
        for (int i = 0; i < 8; i++) {
            FMA2(a2, hs[2 * i], b2[16 + 2 * i]);
            FMA2(a3, hs[2 * i + 1], b2[16 + 2 * i + 1]);
        }
        hb = red4(a0, a1, a2, a3);
    }

    float* Xp = out + (size_t)row * (ITERS + 1) * 128;
    float* Pp = out + (size_t)BSZ * (ITERS + 1) * 128 + (size_t)row * (ITERS + 1) * 32;

    // k = 0 Xs (p(0) is produced by the first primal pair from z(0)=0)
    Xp[lane] = 0.0f; Xp[lane + 32] = 0.0f; Xp[lane + 64] = 0.0f; Xp[lane + 96] = 0.0f;

    // init buffer 0
    sy[w][0][lane] = 0.0f; sy[w][0][lane + 32] = 0.0f;
    sz[w][0][lane] = 0.0f; sz[w][0][lane + 32] = 0.0f;

    float y0 = 0.0f, y1 = 0.0f, z0 = 0.0f, z1 = 0.0f;
    float* xk = Xp + 128;

    const ulonglong2* hsB = (const ulonglong2*)(sHinv + lane * 68 + 32); // 8 x 16B

    // one iteration: read y from buf RB, write y/z to buf WB
#define ITER_BODY(RB, WB)                                                     \
    {                                                                         \
        const ulonglong2* yb = (const ulonglong2*)&sy[w][RB][0];              \
        ull a0 = 0ull, a1 = 0ull, a2 = 0ull, a3 = 0ull;                       \
        ull b0 = 0ull, b1 = 0ull, b2 = 0ull, b3 = 0ull;                       \
        _Pragma("unroll")                                                     \
        for (int i = 0; i < 8; i++) {                                         \
            ulonglong2 p = yb[2 * i];                                         \
            ulonglong2 p2 = yb[2 * i + 1];                                    \
            FMA2(a0, dA2[4 * i + 0], p.x);                                    \
            FMA2(a1, dA2[4 * i + 1], p.y);                                    \
            FMA2(a2, dA2[4 * i + 2], p2.x);                                   \
            FMA2(a3, dA2[4 * i + 3], p2.y);                                   \
            FMA2(b0, dB2[4 * i + 0], p.x);                                    \
            FMA2(b1, dB2[4 * i + 1], p.y);                                    \
            FMA2(b2, dB2[4 * i + 2], p2.x);                                   \
            FMA2(b3, dB2[4 * i + 3], p2.y);                                   \
        }                                                                     \
        float w0 = red4(a0, a1, a2, a3);                                      \
        float w1 = red4(b0, b1, b2, b3);                                      \
        float ny0 = fmaf(c, w0 + z0, mu0);                                    \
        float ny1 = fmaf(c, w1 + z1, mu1);                                    \
        float nz0 = fmaxf(fmaf(-2.0f, ny0, y0 + z0), 0.0f);                   \
        float nz1 = fmaxf(fmaf(-2.0f, ny1, y1 + z1), 0.0f);                   \
        sy[w][WB][lane] = ny0; sy[w][WB][lane + 32] = ny1;                    \
        sz[w][WB][lane] = nz0; sz[w][WB][lane + 32] = nz1;                    \
        y0 = ny0; y1 = ny1; z0 = nz0; z1 = nz1;                               \
        xk[lane] = y0; xk[lane + 32] = y1;                                    \
        xk[lane + 64] = z0; xk[lane + 96] = z1;                               \
        xk += 128;                                                            \
    }

    for (int t2 = 0; t2 < ITERS / 2; t2++) {
        int kA = 2 * t2 + 1;

        ITER_BODY(0, 1)                       // X(kA): y(kA-1) in buf0

        // primal pair: p(kA-1) from z in buf0, p(kA) from z in buf1;
        // each Hinv back-half load serves both.
        {
            const ulonglong2* za = (const ulonglong2*)&sz[w][0][0];
            const ulonglong2* zb = (const ulonglong2*)&sz[w][1][0];
            ull pa0 = 0ull, pa1 = 0ull, pa2 = 0ull, pa3 = 0ull;
            ull pb0 = 0ull, pb1 = 0ull, pb2 = 0ull, pb3 = 0ull;
#pragma unroll
            for (int i = 0; i < 8; i++) {     // front half: hv regs
                ulonglong2 u = za[i];
                FMA2(pa0, hv[2 * i], u.x);
                FMA2(pa1, hv[2 * i + 1], u.y);
                ulonglong2 v = zb[i];
                FMA2(pb0, hv[2 * i], v.x);
                FMA2(pb1, hv[2 * i + 1], v.y);
            }
#pragma unroll
            for (int i = 0; i < 8; i++) {     // back half: shared Hinv, reused x2
                ulonglong2 h = hsB[i];
                ulonglong2 u = za[8 + i];
                FMA2(pa2, h.x, u.x);
                FMA2(pa3, h.y, u.y);
                ulonglong2 v = zb[8 + i];
                FMA2(pb2, h.x, v.x);
                FMA2(pb3, h.y, v.y);
            }
            Pp[(size_t)(kA - 1) * 32 + lane] = red4(pa0, pa1, pa2, pa3) - hb;
            Pp[(size_t)kA * 32 + lane]       = red4(pb0, pb1, pb2, pb3) - hb;
        }

        ITER_BODY(1, 0)                       // X(kA+1): y(kA) in buf1
    }
#undef ITER_BODY

    // drain: p(ITERS) from z(ITERS) in buf0
    {
        const ulonglong2* za = (const ulonglong2*)&sz[w][0][0];
        ull pa0 = 0ull, pa1 = 0ull, pa2 = 0ull, pa3 = 0ull;
#pragma unroll
        for (int i = 0; i < 8; i++) {
            ulonglong2 u = za[i];
            FMA2(pa0, hv[2 * i], u.x);
            FMA2(pa1, hv[2 * i + 1], u.y);
        }
#pragma unroll
        for (int i = 0; i < 8; i++) {
            ulonglong2 h = hsB[i];
            ulonglong2 u = za[8 + i];
            FMA2(pa2, h.x, u.x);
            FMA2(pa3, h.y, u.y);
        }
        Pp[(size_t)ITERS * 32 + lane] = red4(pa0, pa1, pa2, pa3) - hb;
    }
}

extern "C" void kernel_launch(void* const* d_in, const int* in_sizes, int n_in,
                              void* d_out, int out_size) {
    const float *q = nullptr, *b = nullptr, *P = nullptr, *H = nullptr;
    for (int i = 0; i < n_in; i++) {
        switch (in_sizes[i]) {
            case BSZ * NDIM:  q = (const float*)d_in[i]; break;  // 16384
            case BSZ * MDIM:  b = (const float*)d_in[i]; break;  // 32768
            case NDIM * NDIM: P = (const float*)d_in[i]; break;  // 1024
            case MDIM * NDIM: H = (const float*)d_in[i]; break;  // 2048
            default: break;                                      // iters ignored
        }
    }
    setup_kernel<<<1, 256>>>(P, H);
    solve_kernel<<<BSZ / 4, 128>>>(q, b, (float*)d_out);
}